// round 9
// baseline (speedup 1.0000x reference)
#include <cuda_runtime.h>

#define N_    1024
#define M_    1024
#define D_    128
#define NNZ_  32768
#define H_    256
#define GRID_ 1024

typedef unsigned long long u64;

// ---------------- device scratch (no allocations allowed) ----------------
// g_sum/g_cnt zeroed at load; phase 4 restores zero-state each invocation.
// g_bar[0]/g_bar[1] reset in phase 4; g_bar[2] reset in phase 0 of the NEXT
// invocation (ordered via barrier A's release-acquire chain).
__device__ int      g_cnt[M_];
__device__ unsigned g_bar[3];
__device__ __align__(16) float g_sum[M_ * D_];     // raw scatter sums [m][d]
__device__ __align__(16) float g_hxT[H_ * N_];     // [h][n]
__device__ __align__(16) float g_hebT[H_ * M_];    // [h][m] (incl /cnt and +b1)

// ---------------- small helpers ----------------
__device__ __forceinline__ u64 bcast2(float v) {
    u64 r;
    asm("mov.b64 %0, {%1, %1};" : "=l"(r) : "f"(v));
    return r;
}

__device__ __forceinline__ float2 unpack2(u64 v) {
    float lo, hi;
    asm("mov.b64 {%0, %1}, %2;" : "=f"(lo), "=f"(hi) : "l"(v));
    return make_float2(lo, hi);
}

// acc2 += relu(a2 + b2) * w2   (packed f32x2; relu on the scalar halves)
__device__ __forceinline__ void relu_fma2(u64 &acc, u64 a, u64 b, u64 w) {
    asm("{\n\t"
        ".reg .b64 t;\n\t"
        ".reg .f32 lo, hi;\n\t"
        "add.rn.f32x2 t, %1, %2;\n\t"
        "mov.b64 {lo, hi}, t;\n\t"
        "max.f32 lo, lo, 0f00000000;\n\t"
        "max.f32 hi, hi, 0f00000000;\n\t"
        "mov.b64 t, {lo, hi};\n\t"
        "fma.rn.f32x2 %0, t, %3, %0;\n\t"
        "}"
        : "+l"(acc) : "l"(a), "l"(b), "l"(w));
}

__device__ __forceinline__ float sigmoidf_fast(float x) {
    return 1.0f / (1.0f + __expf(-x));
}

// software grid barrier: all GRID_ blocks co-resident by construction
__device__ __forceinline__ void gbar(unsigned* ctr) {
    __syncthreads();
    if (threadIdx.x == 0) {
        unsigned prev;
        asm volatile("atom.add.release.gpu.u32 %0, [%1], 1;"
                     : "=r"(prev) : "l"(ctr) : "memory");
        if (prev + 1 < GRID_) {
            unsigned v;
            do {
                __nanosleep(128);
                asm volatile("ld.acquire.gpu.u32 %0, [%1];"
                             : "=r"(v) : "l"(ctr) : "memory");
            } while (v < GRID_);
        }
    }
    __syncthreads();
}

// ---------------- the one persistent kernel ----------------
__global__ __launch_bounds__(128, 7) void k_fused(const float* __restrict__ X,
                                                  const int* __restrict__ V,
                                                  const int* __restrict__ E,
                                                  const float* __restrict__ W1,
                                                  const float* __restrict__ b1,
                                                  const float* __restrict__ W2,
                                                  const float* __restrict__ b2p,
                                                  float* __restrict__ out) {
    // shared scratch, aliased per phase.
    // phase 2 (gemm): As 16x65 (1040) + Ws 16x32 (512)
    // phase 3 (main): hx 32x64 (2048) + heb 32x64 (2048) + w2 (64)
    __shared__ __align__(16) float sm[4160];

    int bid = blockIdx.x;
    int tid = threadIdx.x;

    // ======== phase 0: init out = b2; reset bar C (from prev invocation) ==
    if (bid == 0 && tid == 0) g_bar[2] = 0;   // ordered by barrier A chain
    {
        float b = __ldg(b2p);
        float4 bv = make_float4(b, b, b, b);
        float4* o4 = (float4*)out;
        o4[bid * 256 + tid]       = bv;
        o4[bid * 256 + 128 + tid] = bv;
    }

    // ======== phase 1: scatter (vector RED into g_sum) ====================
    {
        int gw   = bid * 4 + (tid >> 5);   // 4096 warps, 8 edges each
        int lane = tid & 31;
        #pragma unroll
        for (int j = 0; j < 8; j++) {
            int edge = gw * 8 + j;
            int e = E[edge];
            int v = V[edge];
            float4 x = *(const float4*)&X[v * D_ + lane * 4];
            float* dst = &g_sum[e * D_ + lane * 4];
            asm volatile("red.global.add.v4.f32 [%0], {%1, %2, %3, %4};"
                         :: "l"(dst), "f"(x.x), "f"(x.y), "f"(x.z), "f"(x.w) : "memory");
            if (lane == 0) atomicAdd(&g_cnt[e], 1);
        }
    }

    gbar(&g_bar[0]);   // ======== barrier A ========

    // ======== phase 2: two small GEMMs (256 active blocks) ================
    if (bid < 256) {
        int z  = bid >> 7;               // 0: X@W1a -> hxT ; 1: sum@W1b -> hebT
        int r  = bid & 127;
        int n0 = (r & 15) * 64;
        int h0 = (r >> 4) * 32;
        const float* A    = z ? g_sum  : X;
        float*       outT = z ? g_hebT : g_hxT;
        int dof = z ? D_ : 0;

        float* As = sm;                  // [16][65]
        float* Ws = sm + 1040;           // [16][32]

        int tn = tid & 15;               // n = tn*4
        int th = tid >> 4;               // h = th*4 (0..7 -> 32 h)

        float acc[4][4];
        #pragma unroll
        for (int i = 0; i < 4; i++)
            #pragma unroll
            for (int j = 0; j < 4; j++)
                acc[i][j] = 0.f;

        for (int d0 = 0; d0 < D_; d0 += 16) {
            #pragma unroll
            for (int rr = 0; rr < 8; rr++) {
                int i  = rr * 128 + tid;
                int dk = i & 15;
                int nl = i >> 4;
                As[dk * 65 + nl] = A[(n0 + nl) * D_ + d0 + dk];
            }
            #pragma unroll
            for (int rr = 0; rr < 4; rr++) {
                int i  = rr * 128 + tid;
                int hh = i & 31;
                int dk = i >> 5;
                Ws[dk * 32 + hh] = W1[(dof + d0 + dk) * H_ + h0 + hh];
            }
            __syncthreads();
            #pragma unroll
            for (int dk = 0; dk < 16; dk++) {
                float a[4], w[4];
                #pragma unroll
                for (int i = 0; i < 4; i++) a[i] = As[dk * 65 + tn * 4 + i];
                #pragma unroll
                for (int j = 0; j < 4; j++) w[j] = Ws[dk * 32 + th * 4 + j];
                #pragma unroll
                for (int i = 0; i < 4; i++)
                    #pragma unroll
                    for (int j = 0; j < 4; j++)
                        acc[i][j] = fmaf(a[i], w[j], acc[i][j]);
            }
            __syncthreads();
        }

        float scale[4] = {1.f, 1.f, 1.f, 1.f};
        if (z) {
            #pragma unroll
            for (int i = 0; i < 4; i++) {
                int c = g_cnt[n0 + tn * 4 + i];
                scale[i] = 1.0f / ((c > 0) ? (float)c : 1.0f);
            }
        }
        #pragma unroll
        for (int j = 0; j < 4; j++) {
            int h = h0 + th * 4 + j;
            float bb = z ? b1[h] : 0.f;
            float4 v = make_float4(acc[0][j] * scale[0] + bb,
                                   acc[1][j] * scale[1] + bb,
                                   acc[2][j] * scale[2] + bb,
                                   acc[3][j] * scale[3] + bb);
            *(float4*)&outT[h * N_ + n0 + tn * 4] = v;
        }
    }

    gbar(&g_bar[1]);   // ======== barrier B ========

    // ======== phase 3: main N x M x H contraction (exact R3 loop) =========
    {
        float* hx_s  = sm;           // [32][64]
        float* heb_s = sm + 2048;    // [32][64]
        float* w2_s  = sm + 4096;    // [64]

        int hb  = (bid & 3) * 64;
        int m0  = ((bid >> 2) & 15) * 64;
        int n0  = (bid >> 6) * 64;
        int tn  = tid & 15;          // n base = tn*4
        int tm  = tid >> 4;          // m base = tm*8

        u64 acc[4][4];               // [ni][mpair]
        #pragma unroll
        for (int i = 0; i < 4; i++)
            #pragma unroll
            for (int p = 0; p < 4; p++)
                acc[i][p] = 0ull;

        if (tid < 64) w2_s[tid] = W2[hb + tid];

        int cg = tid & 15;
        int r0 = tid >> 4;

        for (int sc = 0; sc < 2; sc++) {
            int hbase = hb + sc * 32;
            #pragma unroll
            for (int k = 0; k < 4; k++) {
                int hh = k * 8 + r0;
                *(float4*)&hx_s[hh * 64 + cg * 4]  = *(const float4*)&g_hxT[(hbase + hh) * N_ + n0 + cg * 4];
                *(float4*)&heb_s[hh * 64 + cg * 4] = *(const float4*)&g_hebT[(hbase + hh) * M_ + m0 + cg * 4];
            }
            __syncthreads();

            #pragma unroll 4
            for (int hh = 0; hh < 32; hh++) {
                float4 hx4 = *(const float4*)&hx_s[hh * 64 + tn * 4];
                ulonglong2 e0 = *(const ulonglong2*)&heb_s[hh * 64 + tm * 8];
                ulonglong2 e1 = *(const ulonglong2*)&heb_s[hh * 64 + tm * 8 + 4];
                u64 w2p = bcast2(w2_s[sc * 32 + hh]);
                u64 q0 = bcast2(hx4.x);
                u64 q1 = bcast2(hx4.y);
                u64 q2 = bcast2(hx4.z);
                u64 q3 = bcast2(hx4.w);

                relu_fma2(acc[0][0], e0.x, q0, w2p);
                relu_fma2(acc[0][1], e0.y, q0, w2p);
                relu_fma2(acc[0][2], e1.x, q0, w2p);
                relu_fma2(acc[0][3], e1.y, q0, w2p);

                relu_fma2(acc[1][0], e0.x, q1, w2p);
                relu_fma2(acc[1][1], e0.y, q1, w2p);
                relu_fma2(acc[1][2], e1.x, q1, w2p);
                relu_fma2(acc[1][3], e1.y, q1, w2p);

                relu_fma2(acc[2][0], e0.x, q2, w2p);
                relu_fma2(acc[2][1], e0.y, q2, w2p);
                relu_fma2(acc[2][2], e1.x, q2, w2p);
                relu_fma2(acc[2][3], e1.y, q2, w2p);

                relu_fma2(acc[3][0], e0.x, q3, w2p);
                relu_fma2(acc[3][1], e0.y, q3, w2p);
                relu_fma2(acc[3][2], e1.x, q3, w2p);
                relu_fma2(acc[3][3], e1.y, q3, w2p);
            }
            __syncthreads();
        }

        #pragma unroll
        for (int i = 0; i < 4; i++) {
            int n = n0 + tn * 4 + i;
            float2 a = unpack2(acc[i][0]);
            float2 b = unpack2(acc[i][1]);
            float2 c = unpack2(acc[i][2]);
            float2 d = unpack2(acc[i][3]);
            float* dst = &out[n * M_ + m0 + tm * 8];
            asm volatile("red.global.add.v4.f32 [%0], {%1, %2, %3, %4};"
                         :: "l"(dst), "f"(a.x), "f"(a.y), "f"(b.x), "f"(b.y) : "memory");
            asm volatile("red.global.add.v4.f32 [%0], {%1, %2, %3, %4};"
                         :: "l"(dst + 4), "f"(c.x), "f"(c.y), "f"(d.x), "f"(d.y) : "memory");
        }
    }

    gbar(&g_bar[2]);   // ======== barrier C ========

    // ======== phase 4: sigmoid in place + re-zero scratch for next call ===
    {
        int gi = bid * 128 + tid;
        if (gi < (M_ * D_) / 4) ((float4*)g_sum)[gi] = make_float4(0.f, 0.f, 0.f, 0.f);
        if (gi < M_) g_cnt[gi] = 0;
        if (bid == 0 && tid == 0) { g_bar[0] = 0; g_bar[1] = 0; }

        float4* o4 = (float4*)out;
        #pragma unroll
        for (int k = 0; k < 2; k++) {
            int idx = bid * 256 + k * 128 + tid;
            float* p = (float*)&o4[idx];
            float4 v;
            asm volatile("ld.global.cg.v4.f32 {%0,%1,%2,%3}, [%4];"
                         : "=f"(v.x), "=f"(v.y), "=f"(v.z), "=f"(v.w) : "l"(p));
            v.x = sigmoidf_fast(v.x);
            v.y = sigmoidf_fast(v.y);
            v.z = sigmoidf_fast(v.z);
            v.w = sigmoidf_fast(v.w);
            o4[idx] = v;
        }
    }
}

// ---------------- launch ----------------
extern "C" void kernel_launch(void* const* d_in, const int* in_sizes, int n_in,
                              void* d_out, int out_size) {
    const float* X  = (const float*)d_in[0];
    const int*   V  = (const int*)d_in[1];
    const int*   E  = (const int*)d_in[2];
    const float* W1 = (const float*)d_in[3];
    const float* b1 = (const float*)d_in[4];
    const float* W2 = (const float*)d_in[5];
    const float* b2 = (const float*)d_in[6];
    float* out = (float*)d_out;

    k_fused<<<GRID_, 128>>>(X, V, E, W1, b1, W2, b2, out);
}